// round 16
// baseline (speedup 1.0000x reference)
#include <cuda_runtime.h>
#include <cstdint>

#define B_ 8
#define N_ 8192
#define Q_ 1024
#define S_ 32
#define M_ (B_*Q_*S_)          // 262144
#define R2_ 0.04f
#define ALPHA_ 0.2f
#define EPS_ 1e-5f

// ---------------- scratch (device globals: no allocations allowed) ----------------
__device__ float g_y0[(size_t)64*M_];          // layer0 raw output
__device__ float g_y1[(size_t)128*M_];         // layer1 raw output
__device__ float g_ft[(size_t)B_*N_*64];       // features transposed [B][N][64]
__device__ float g_gmax[(size_t)256*B_*Q_];    // layer2 max over S (pre-BN)
__device__ int   g_nidx[M_];                   // ball query indices
__device__ float g_st0[2*64], g_st1[2*128], g_st2[2*256];   // [sum | sumsq]
__device__ float g_ac0[2*64], g_ac1[2*128], g_ac2[2*256];   // [a | c] per channel
__device__ float g_wt0[96*64];                 // W0^T (tf32, CHANNEL-PERMUTED: ft first, rel at k=64..66)
__device__ float g_wt1[64*128];                // W1^T
__device__ float g_wt2[128*256];               // W2^T
// FPS cross-block slots: [batch][part][parity] = val(32)|idx(13)|tag(10)
__device__ volatile unsigned long long g_fps[B_][4][2];

__device__ __forceinline__ float lrelu(float v){ return v >= 0.f ? v : ALPHA_*v; }

// tf32 quantization (cuBLAS-style round-to-nearest)
__device__ __forceinline__ float tf32r(float x){
    unsigned r; asm("cvt.rna.tf32.f32 %0, %1;" : "=r"(r) : "f"(x));
    return __uint_as_float(r);
}

typedef unsigned long long u64;
__device__ __forceinline__ u64 fma2n(u64 a, u64 b, u64 c){
    u64 d; asm("fma.rn.f32x2 %0, %1, %2, %3;" : "=l"(d) : "l"(a), "l"(b), "l"(c)); return d;
}
__device__ __forceinline__ u64 add2(u64 a, u64 b){
    u64 d; asm("add.rn.f32x2 %0, %1, %2;" : "=l"(d) : "l"(a), "l"(b)); return d;
}
__device__ __forceinline__ u64 mul2(u64 a, u64 b){
    u64 d; asm("mul.rn.f32x2 %0, %1, %2;" : "=l"(d) : "l"(a), "l"(b)); return d;
}
__device__ __forceinline__ u64 pack2(float lo, float hi){
    u64 d; asm("mov.b64 %0, {%1,%2};" : "=l"(d) : "f"(lo), "f"(hi)); return d;
}
__device__ __forceinline__ u64 splat2(float v){
    u64 d; asm("mov.b64 %0, {%1,%1};" : "=l"(d) : "f"(v)); return d;
}
__device__ __forceinline__ float2 u2f2(u64 u){
    float2 f; asm("mov.b64 {%0,%1}, %2;" : "=f"(f.x), "=f"(f.y) : "l"(u)); return f;
}

// legacy tensor-core mma (sm_80+, valid on compute_100 baseline target)
__device__ __forceinline__ void mma_tf32(float* d, uint32_t a0, uint32_t a1,
                                         uint32_t a2, uint32_t a3,
                                         uint32_t b0, uint32_t b1){
    asm volatile(
        "mma.sync.aligned.m16n8k8.row.col.f32.tf32.tf32.f32 "
        "{%0,%1,%2,%3}, {%4,%5,%6,%7}, {%8,%9}, {%0,%1,%2,%3};"
        : "+f"(d[0]), "+f"(d[1]), "+f"(d[2]), "+f"(d[3])
        : "r"(a0), "r"(a1), "r"(a2), "r"(a3), "r"(b0), "r"(b1));
}

// argmax step across 32 index-ordered candidates (values >= 0)
__device__ __forceinline__ void warp_argmax(float &best, int &bi){
    unsigned bb = __float_as_uint(best);
    unsigned mx = __reduce_max_sync(0xffffffffu, bb);
    unsigned who = __ballot_sync(0xffffffffu, bb == mx);
    int src = __ffs(who) - 1;
    bi = __shfl_sync(0xffffffffu, bi, src);
    best = __uint_as_float(mx);
}

// ---------------- FPS: 4 blocks per batch, lockstep via global slots ----------------
// Each block owns 2048 points (2/thread). Per iter: block-local argmax (two-stage),
// publish one u64 (val|idx|tag) to parity buffer, all warps poll 4 slots, combine in
// block order (ascending + strict > = global first-occurrence ties). Max skew between
// blocks is 1 iter -> double buffer safe. Slots tag-cleared at start (replay-safe).
__global__ void __launch_bounds__(1024) fps_kernel(const float* __restrict__ xyz,
                                                   float* __restrict__ newxyz){
    int bid = blockIdx.x;
    int b = bid >> 2, part = bid & 3;
    int t = threadIdx.x;
    int wid = t >> 5, lane = t & 31;
    const float* px = xyz + (size_t)b*N_*3;
    int p0 = part*2048 + t*2;
    u64 X2 = pack2(px[p0*3+0], px[p0*3+3]);
    u64 Y2 = pack2(px[p0*3+1], px[p0*3+4]);
    u64 Z2 = pack2(px[p0*3+2], px[p0*3+5]);
    float D0 = 1e10f, D1 = 1e10f;
    __shared__ float s_val[2][32];
    __shared__ int   s_idx[2][32];
    float lx = px[0], ly = px[1], lz = px[2];
    if (t == 0){
        g_fps[b][part][0] = 0ull;   // clear stale tags from prior replay
        g_fps[b][part][1] = 0ull;
        if (part == 0){
            newxyz[(size_t)b*Q_*3 + 0] = lx;
            newxyz[(size_t)b*Q_*3 + 1] = ly;
            newxyz[(size_t)b*Q_*3 + 2] = lz;
        }
    }
    __syncthreads();
    for (int j = 1; j < Q_; j++){
        int par = j & 1;
        u64 nlx = splat2(-lx), nly = splat2(-ly), nlz = splat2(-lz);
        u64 dx = add2(X2, nlx);
        u64 dy = add2(Y2, nly);
        u64 dz = add2(Z2, nlz);
        u64 tt = mul2(dx, dx);
        tt = fma2n(dy, dy, tt);
        tt = fma2n(dz, dz, tt);
        float2 dd = u2f2(tt);
        D0 = fminf(D0, dd.x);
        D1 = fminf(D1, dd.y);
        float vbest = fmaxf(D0, D1);
        unsigned mx = __reduce_max_sync(0xffffffffu, __float_as_uint(vbest));
        unsigned who = __ballot_sync(0xffffffffu, __float_as_uint(vbest) == mx);
        int src = __ffs(who) - 1;
        int bi = 0;
        if (lane == src){                       // descending overwrite -> lowest index
            if (__float_as_uint(D1) == mx) bi = p0 + 1;
            if (__float_as_uint(D0) == mx) bi = p0;
        }
        bi = __shfl_sync(0xffffffffu, bi, src);
        if (lane == 0){ s_val[par][wid] = __uint_as_float(mx); s_idx[par][wid] = bi; }
        __syncthreads();
        float best = s_val[par][lane]; bi = s_idx[par][lane];
        warp_argmax(best, bi);                  // block-local winner (all warps agree)
        if (t == 0)
            g_fps[b][part][par] = ((u64)__float_as_uint(best) << 32)
                                | ((u64)(unsigned)bi << 10) | (u64)(unsigned)j;
        // poll all 4 parts (lanes 0-3), every warp independently
        u64 w = 0;
        bool mine = lane < 4;
        for (;;){
            if (mine) w = g_fps[b][lane][par];
            bool ok = !mine || ((unsigned)(w & 1023u) == (unsigned)j);
            if (__all_sync(0xffffffffu, ok)) break;
        }
        unsigned bv = 0u; int gbi = 0;
#pragma unroll
        for (int k2 = 0; k2 < 4; k2++){
            u64 wk = __shfl_sync(0xffffffffu, w, k2);
            unsigned v = (unsigned)(wk >> 32);
            int ix = (int)((wk >> 10) & 0x1FFFu);
            if (v > bv){ bv = v; gbi = ix; }    // ascending block order keeps ties right
        }
        const float* pp = px + (size_t)gbi*3;
        lx = pp[0]; ly = pp[1]; lz = pp[2];
        if (part == 0 && t == 0){
            float* o = newxyz + (size_t)(b*Q_ + j)*3;
            o[0] = lx; o[1] = ly; o[2] = lz;
        }
    }
}

// ---------------- Ball query: one warp per (b,q), XLA-matched rounding ----------------
__global__ void __launch_bounds__(256) ballquery_kernel(const float* __restrict__ xyz,
                                                        const float* __restrict__ newxyz,
                                                        int* __restrict__ nidx){
    int w = (blockIdx.x*256 + threadIdx.x) >> 5;
    int lane = threadIdx.x & 31;
    int b = w >> 10;
    const float* px = xyz + (size_t)b*N_*3;
    const float* pq = newxyz + (size_t)w*3;
    float qx=pq[0], qy=pq[1], qz=pq[2];
    float qsq = __fadd_rn(__fadd_rn(__fmul_rn(qx,qx), __fmul_rn(qy,qy)), __fmul_rn(qz,qz));
    int* out = nidx + (size_t)w*S_;
    int cnt = 0, first = 0;
    for (int base=0; base<N_ && cnt<S_; base+=32){
        int p = base + lane;
        float x=px[p*3+0], y=px[p*3+1], z=px[p*3+2];
        float xsq = __fadd_rn(__fadd_rn(__fmul_rn(x,x), __fmul_rn(y,y)), __fmul_rn(z,z));
        float dot = __fmaf_rn(qz, z, __fmaf_rn(qy, y, __fmul_rn(qx, x)));
        float d2  = __fadd_rn(__fadd_rn(qsq, xsq), __fmul_rn(-2.0f, dot));
        bool in = d2 < R2_;
        unsigned bal = __ballot_sync(0xffffffffu, in);
        if (bal){
            if (cnt == 0) first = base + __ffs(bal) - 1;
            int r = __popc(bal & ((1u << lane) - 1u));
            if (in && (cnt + r < S_)) out[cnt + r] = p;
            cnt += __popc(bal);
        }
    }
    if (cnt < S_){
        int pad = (cnt > 0) ? first : 0;
        if (lane >= cnt) out[lane] = pad;
    }
}

// ---------------- merged prep: transpose_feat + 3x transpose_w + zero_stats ----------------
__global__ void __launch_bounds__(256) prep_kernel(
    const float* __restrict__ f, float* __restrict__ ft,
    const float* __restrict__ W0, float* __restrict__ WT0,
    const float* __restrict__ W1, float* __restrict__ WT1,
    const float* __restrict__ W2, float* __restrict__ WT2)
{
    int blk = blockIdx.x;
    int tid = threadIdx.x;
    if (blk < 2048){
        __shared__ float st[64][33];
        int b = blk >> 8;
        int n0 = (blk & 255) * 32;
        int nn = tid & 31, c0 = tid >> 5;
#pragma unroll
        for (int c = c0; c < 64; c += 8)
            st[c][nn] = f[((size_t)b*64 + c)*N_ + n0 + nn];
        __syncthreads();
#pragma unroll
        for (int e = tid; e < 2048; e += 256){
            int nl = e >> 6, c = e & 63;
            ft[((size_t)b*N_ + n0 + nl)*64 + c] = st[c][nl];
        }
        return;
    }
    int idx = (blk - 2048)*256 + tid;
    if (idx < 6144){                               // W0^T: 96x64, PERMUTED channels
        int k = idx / 64, c = idx - k*64;
        int ks = (k < 64) ? (k + 3) : ((k < 67) ? (k - 64) : -1);
        WT0[idx] = (ks >= 0) ? tf32r(W0[c*67 + ks]) : 0.f;
    } else if (idx < 6144 + 8192){                 // W1^T: 64x128
        int i2 = idx - 6144;
        int k = i2 / 128, c = i2 - k*128;
        WT1[i2] = tf32r(W1[c*64 + k]);
    } else if (idx < 6144 + 8192 + 32768){         // W2^T: 128x256
        int i2 = idx - 6144 - 8192;
        int k = i2 / 256, c = i2 - k*256;
        WT2[i2] = tf32r(W2[c*128 + k]);
    } else if (idx < 6144 + 8192 + 32768 + 896){   // zero stats
        int i2 = idx - 6144 - 8192 - 32768;
        if (i2 < 128)      g_st0[i2] = 0.f;
        else if (i2 < 384) g_st1[i2-128] = 0.f;
        else               g_st2[i2-384] = 0.f;
    }
}

#define PW0 36  // l0 pitch: 16B-aligned rows for float4 fill; fragment LDS conflict-free
#define PWG 37  // generic pitch: scalar fill 2-way (vs 16-way at 36); fragment LDS conflict-free

// ---------------- L0 GEMM, fused VECTORIZED gather ----------------
// Channel order: k=0..63 ft (aligned float4 gather), k=64..66 rel-xyz, rest pad.
__global__ void __launch_bounds__(256,2) mma_gemm_l0(
    const float* __restrict__ WT, const float* __restrict__ bias,
    const float* __restrict__ xyz, const float* __restrict__ nxyz,
    const float* __restrict__ ft, const int* __restrict__ nidx,
    float* __restrict__ Yout, float* __restrict__ gstats)
{
    constexpr int WY=4, WX=2, NT=8;
    constexpr int CTILE = WY*16;    // 64
    constexpr int MT = WX*NT*8;     // 128
    constexpr int NCH = 3;          // KPAD=96
    __shared__ __align__(16) float sW[CTILE*PW0];
    __shared__ __align__(16) float sX[MT*PW0];
    int tid = threadIdx.x;
    int wid = tid >> 5, lane = tid & 31;
    int wy = wid % WY, wx = wid / WY;
    int mbase = blockIdx.x * MT;
    int qr = lane >> 2, ql = lane & 3;
    int mwarp = wx*NT*8;

    int mloc = tid & 127;
    int half = tid >> 7;                 // 0: kk 0-15, 1: kk 16-31
    int m = mbase + mloc;
    int gb = m >> 15;
    int gq = (m >> 5) & (Q_-1);
    int p = nidx[m];
    const float* pc = xyz + ((size_t)gb*N_ + p)*3;
    const float* qc = nxyz + ((size_t)(gb*Q_ + gq))*3;
    float rel0 = pc[0]-qc[0], rel1 = pc[1]-qc[1], rel2 = pc[2]-qc[2];
    const float* fr = ft + ((size_t)gb*N_ + p)*64;

    float d[NT][4];
#pragma unroll
    for (int i=0;i<NT;i++){ d[i][0]=0.f; d[i][1]=0.f; d[i][2]=0.f; d[i][3]=0.f; }

#pragma unroll 1
    for (int ch = 0; ch < NCH; ++ch){
        int k0 = ch*32;
        __syncthreads();
#pragma unroll
        for (int e = tid; e < CTILE*8; e += 256){
            int kk = e / (CTILE/4), c4 = e % (CTILE/4);
            float4 w = *(const float4*)&WT[(size_t)(k0+kk)*64 + c4*4];
            sW[(c4*4+0)*PW0 + kk] = w.x;
            sW[(c4*4+1)*PW0 + kk] = w.y;
            sW[(c4*4+2)*PW0 + kk] = w.z;
            sW[(c4*4+3)*PW0 + kk] = w.w;
        }
        if (ch < 2){
            const float4* f4 = (const float4*)(fr + ch*32 + half*16);
#pragma unroll
            for (int j=0;j<4;j++){
                float4 v = f4[j];
                v.x=tf32r(v.x); v.y=tf32r(v.y); v.z=tf32r(v.z); v.w=tf32r(v.w);
                *(float4*)&sX[mloc*PW0 + half*16 + j*4] = v;
            }
        } else {
            float4 z = make_float4(0.f,0.f,0.f,0.f);
            if (half==0){
                *(float4*)&sX[mloc*PW0 + 0]  = make_float4(tf32r(rel0), tf32r(rel1), tf32r(rel2), 0.f);
                *(float4*)&sX[mloc*PW0 + 4]  = z;
                *(float4*)&sX[mloc*PW0 + 8]  = z;
                *(float4*)&sX[mloc*PW0 + 12] = z;
            } else {
#pragma unroll
                for (int j=0;j<4;j++) *(float4*)&sX[mloc*PW0 + 16 + j*4] = z;
            }
        }
        __syncthreads();
#pragma unroll
        for (int s = 0; s < 4; ++s){
            int kb = s*8 + ql;
            const float* w0 = &sW[(wy*16 + qr)*PW0];
            const float* w8 = &sW[(wy*16 + qr + 8)*PW0];
            uint32_t a0 = __float_as_uint(w0[kb]);
            uint32_t a1 = __float_as_uint(w8[kb]);
            uint32_t a2 = __float_as_uint(w0[kb+4]);
            uint32_t a3 = __float_as_uint(w8[kb+4]);
#pragma unroll
            for (int nt = 0; nt < NT; ++nt){
                const float* xb = &sX[(mwarp + nt*8 + qr)*PW0 + s*8 + ql];
                uint32_t b0 = __float_as_uint(xb[0]);
                uint32_t b1 = __float_as_uint(xb[4]);
                mma_tf32(d[nt], a0, a1, a2, a3, b0, b1);
            }
        }
    }

    int cout0 = wy*16 + qr;
    int cout1 = cout0 + 8;
    float bi0 = bias[cout0], bi1 = bias[cout1];
    float s1a=0.f, s2a=0.f, s1b=0.f, s2b=0.f;
#pragma unroll
    for (int nt = 0; nt < NT; ++nt){
        float v0 = d[nt][0] + bi0, v1 = d[nt][1] + bi0;
        float v2 = d[nt][2] + bi1, v3 = d[nt][3] + bi1;
        s1a += v0 + v1;  s2a += v0*v0 + v1*v1;
        s1b += v2 + v3;  s2b += v2*v2 + v3*v3;
        int m0 = mbase + mwarp + nt*8 + ql*2;
        *(float2*)(Yout + (size_t)cout0*M_ + m0) = make_float2(v0, v1);
        *(float2*)(Yout + (size_t)cout1*M_ + m0) = make_float2(v2, v3);
    }
#pragma unroll
    for (int o=1;o<4;o<<=1){
        s1a += __shfl_xor_sync(0xffffffffu, s1a, o);
        s2a += __shfl_xor_sync(0xffffffffu, s2a, o);
        s1b += __shfl_xor_sync(0xffffffffu, s1b, o);
        s2b += __shfl_xor_sync(0xffffffffu, s2b, o);
    }
    if (ql == 0){
        atomicAdd(&gstats[cout0], s1a);
        atomicAdd(&gstats[64 + cout0], s2a);
        atomicAdd(&gstats[cout1], s1b);
        atomicAdd(&gstats[64 + cout1], s2b);
    }
}

// ---------------- Generic GEMM via mma.sync m16n8k8 TF32 (PW=37, R12-proven) ----------------
template<int CIN, int KPAD, int WY, int WX, int NT, bool TRANS, bool DOMAX, int COUTTOT>
__global__ void __launch_bounds__(256,2) mma_gemm(
    const float* __restrict__ WT, const float* __restrict__ bias,
    const float* __restrict__ Xin, const float* __restrict__ ac,
    float* __restrict__ Yout, float* __restrict__ gstats, float* __restrict__ gmax)
{
    constexpr int CTILE = WY*16;
    constexpr int MT = WX*NT*8;
    constexpr int NCH = KPAD/32;
    __shared__ float sW[CTILE*PWG];
    __shared__ float sX[MT*PWG];
    int tid = threadIdx.x;
    int wid = tid >> 5, lane = tid & 31;
    int wy = wid % WY, wx = wid / WY;
    int mbase = blockIdx.x * MT;
    int cbase = blockIdx.y * CTILE;
    int qr = lane >> 2, ql = lane & 3;
    int mwarp = wx*NT*8;

    float d[NT][4];
#pragma unroll
    for (int i=0;i<NT;i++){ d[i][0]=0.f; d[i][1]=0.f; d[i][2]=0.f; d[i][3]=0.f; }

#pragma unroll 1
    for (int ch = 0; ch < NCH; ++ch){
        int k0 = ch*32;
        __syncthreads();
#pragma unroll
        for (int e = tid; e < CTILE*8; e += 256){
            int kk = e / (CTILE/4), c4 = e % (CTILE/4);
            float4 w = *(const float4*)&WT[(size_t)(k0+kk)*COUTTOT + cbase + c4*4];
            sW[(c4*4+0)*PWG + kk] = w.x;
            sW[(c4*4+1)*PWG + kk] = w.y;
            sW[(c4*4+2)*PWG + kk] = w.z;
            sW[(c4*4+3)*PWG + kk] = w.w;
        }
#pragma unroll
        for (int e = tid; e < MT*8; e += 256){
            int kk = e / (MT/4), m4 = e % (MT/4);
            int k = k0 + kk;
            float4 v = make_float4(0.f,0.f,0.f,0.f);
            if (k < CIN){
                v = *(const float4*)(Xin + (size_t)k*M_ + mbase + m4*4);
                if constexpr (TRANS){
                    float a = ac[k], c2 = ac[CIN + k];
                    v.x = lrelu(a*v.x + c2);
                    v.y = lrelu(a*v.y + c2);
                    v.z = lrelu(a*v.z + c2);
                    v.w = lrelu(a*v.w + c2);
                }
                v.x = tf32r(v.x); v.y = tf32r(v.y);
                v.z = tf32r(v.z); v.w = tf32r(v.w);
            }
            sX[(m4*4+0)*PWG + kk] = v.x;
            sX[(m4*4+1)*PWG + kk] = v.y;
            sX[(m4*4+2)*PWG + kk] = v.z;
            sX[(m4*4+3)*PWG + kk] = v.w;
        }
        __syncthreads();
#pragma unroll
        for (int s = 0; s < 4; ++s){
            int kb = s*8 + ql;
            const float* w0 = &sW[(wy*16 + qr)*PWG];
            const float* w8 = &sW[(wy*16 + qr + 8)*PWG];
            uint32_t a0 = __float_as_uint(w0[kb]);
            uint32_t a1 = __float_as_uint(w8[kb]);
            uint32_t a2 = __float_as_uint(w0[kb+4]);
            uint32_t a3 = __float_as_uint(w8[kb+4]);
#pragma unroll
            for (int nt = 0; nt < NT; ++nt){
                const float* xb = &sX[(mwarp + nt*8 + qr)*PWG + s*8 + ql];
                uint32_t b0 = __float_as_uint(xb[0]);
                uint32_t b1 = __float_as_uint(xb[4]);
                mma_tf32(d[nt], a0, a1, a2, a3, b0, b1);
            }
        }
    }

    // -------- epilogue --------
    int cout0 = cbase + wy*16 + qr;
    int cout1 = cout0 + 8;
    float bi0 = bias[cout0], bi1 = bias[cout1];
    float s1a=0.f, s2a=0.f, s1b=0.f, s2b=0.f;
    float mxa[NT/4], mxb[NT/4];
#pragma unroll
    for (int g=0; g<NT/4; ++g){ mxa[g] = -1e30f; mxb[g] = -1e30f; }
#pragma unroll
    for (int nt = 0; nt < NT; ++nt){
        float v0 = d[nt][0] + bi0, v1 = d[nt][1] + bi0;
        float v2 = d[nt][2] + bi1, v3 = d[nt][3] + bi1;
        s1a += v0 + v1;  s2a += v0*v0 + v1*v1;
        s1b += v2 + v3;  s2b += v2*v2 + v3*v3;
        if constexpr (DOMAX){
            int g = nt >> 2;
            mxa[g] = fmaxf(mxa[g], fmaxf(v0, v1));
            mxb[g] = fmaxf(mxb[g], fmaxf(v2, v3));
        } else {
            int m0 = mbase + mwarp + nt*8 + ql*2;
            *(float2*)(Yout + (size_t)cout0*M_ + m0) = make_float2(v0, v1);
            *(float2*)(Yout + (size_t)cout1*M_ + m0) = make_float2(v2, v3);
        }
    }
#pragma unroll
    for (int o=1;o<4;o<<=1){
        s1a += __shfl_xor_sync(0xffffffffu, s1a, o);
        s2a += __shfl_xor_sync(0xffffffffu, s2a, o);
        s1b += __shfl_xor_sync(0xffffffffu, s1b, o);
        s2b += __shfl_xor_sync(0xffffffffu, s2b, o);
    }
    if constexpr (DOMAX){
#pragma unroll
        for (int g=0; g<NT/4; ++g){
#pragma unroll
            for (int o=1;o<4;o<<=1){
                mxa[g] = fmaxf(mxa[g], __shfl_xor_sync(0xffffffffu, mxa[g], o));
                mxb[g] = fmaxf(mxb[g], __shfl_xor_sync(0xffffffffu, mxb[g], o));
            }
        }
        if (ql == 0){
            int sg = (mbase + mwarp) >> 5;
#pragma unroll
            for (int g=0; g<NT/4; ++g){
                gmax[(size_t)cout0*(B_*Q_) + sg + g] = mxa[g];
                gmax[(size_t)cout1*(B_*Q_) + sg + g] = mxb[g];
            }
        }
    }
    if (ql == 0){
        atomicAdd(&gstats[cout0], s1a);
        atomicAdd(&gstats[COUTTOT + cout0], s2a);
        atomicAdd(&gstats[cout1], s1b);
        atomicAdd(&gstats[COUTTOT + cout1], s2b);
    }
}

template<int COUT>
__global__ void compute_ac(const float* __restrict__ st, const float* __restrict__ g,
                           const float* __restrict__ beta, float* __restrict__ ac){
    int c = threadIdx.x;
    if (c >= COUT) return;
    float inv  = 1.f/(float)M_;
    float mean = st[c]*inv;
    float var  = st[COUT+c]*inv - mean*mean;
    float a    = g[c]*rsqrtf(var + EPS_);
    ac[c]      = a;
    ac[COUT+c] = beta[c] - a*mean;
}

// out[b][c][q] = leaky(a2[c]*max + c2[c])   (BN+LeakyReLU commute with max since a2>0)
__global__ void __launch_bounds__(256) final_kernel(const float* __restrict__ gmax,
                                                    const float* __restrict__ ac,
                                                    float* __restrict__ out){
    int i = blockIdx.x*256 + threadIdx.x;
    int q = i & (Q_-1);
    int c = (i >> 10) & 255;
    int b = i >> 18;
    float a = ac[c], c2 = ac[256+c];
    out[i] = lrelu(a*gmax[(size_t)c*(B_*Q_) + b*Q_ + q] + c2);
}

extern "C" void kernel_launch(void* const* d_in, const int* in_sizes, int n_in,
                              void* d_out, int out_size) {
    const float* xyz  = (const float*)d_in[0];
    const float* feat = (const float*)d_in[1];
    const float* W0 = (const float*)d_in[2];
    const float* b0 = (const float*)d_in[3];
    const float* gg0= (const float*)d_in[4];
    const float* be0= (const float*)d_in[5];
    const float* W1 = (const float*)d_in[6];
    const float* b1 = (const float*)d_in[7];
    const float* gg1= (const float*)d_in[8];
    const float* be1= (const float*)d_in[9];
    const float* W2 = (const float*)d_in[10];
    const float* b2 = (const float*)d_in[11];
    const float* gg2= (const float*)d_in[12];
    const float* be2= (const float*)d_in[13];

    float* out = (float*)d_out;
    float* newxyz  = out;                          // [B][Q][3]
    float* outfeat = out + (size_t)B_*Q_*3;        // [B][256][Q]

    float *y0p,*y1p,*ftp,*gmaxp,*st0p,*st1p,*st2p,*ac0p,*ac1p,*ac2p;
    float *wt0p,*wt1p,*wt2p; int* idxp;
    cudaGetSymbolAddress((void**)&y0p,  g_y0);
    cudaGetSymbolAddress((void**)&y1p,  g_y1);
    cudaGetSymbolAddress((void**)&ftp,  g_ft);
    cudaGetSymbolAddress((void**)&gmaxp,g_gmax);
    cudaGetSymbolAddress((void**)&idxp, g_nidx);
    cudaGetSymbolAddress((void**)&st0p, g_st0);
    cudaGetSymbolAddress((void**)&st1p, g_st1);
    cudaGetSymbolAddress((void**)&st2p, g_st2);
    cudaGetSymbolAddress((void**)&ac0p, g_ac0);
    cudaGetSymbolAddress((void**)&ac1p, g_ac1);
    cudaGetSymbolAddress((void**)&ac2p, g_ac2);
    cudaGetSymbolAddress((void**)&wt0p, g_wt0);
    cudaGetSymbolAddress((void**)&wt1p, g_wt1);
    cudaGetSymbolAddress((void**)&wt2p, g_wt2);

    prep_kernel<<<2048 + 188, 256>>>(feat, ftp, W0, wt0p, W1, wt1p, W2, wt2p);
    fps_kernel<<<4*B_, 1024>>>(xyz, newxyz);       // 4 blocks/batch, lockstep
    ballquery_kernel<<<(B_*Q_)/8, 256>>>(xyz, newxyz, idxp);

    // L0 in profiled slot #4: fused vectorized gather, 64 cout x 128 m
    mma_gemm_l0<<<M_/128, 256>>>(wt0p, b0, xyz, newxyz, ftp, idxp, y0p, st0p);
    compute_ac<64><<<1, 64>>>(st0p, gg0, be0, ac0p);

    // L1: 128 cout x 64 m
    mma_gemm<64,64,8,1,8,true,false,128><<<dim3(M_/64, 1), 256>>>(
        wt1p, b1, y0p, ac0p, y1p, st1p, nullptr);
    compute_ac<128><<<1, 128>>>(st1p, gg1, be1, ac1p);

    // L2: 2 tiles of 128 cout x 64 m, fused max-over-S
    mma_gemm<128,128,8,1,8,true,true,256><<<dim3(M_/64, 2), 256>>>(
        wt2p, b2, y1p, ac1p, nullptr, st2p, gmaxp);
    compute_ac<256><<<1, 256>>>(st2p, gg2, be2, ac2p);

    final_kernel<<<(B_*256*Q_)/256, 256>>>(gmaxp, ac2p, outfeat);
}

// round 17
// speedup vs baseline: 3.1653x; 3.1653x over previous
#include <cuda_runtime.h>
#include <cstdint>

#define B_ 8
#define N_ 8192
#define Q_ 1024
#define S_ 32
#define M_ (B_*Q_*S_)          // 262144
#define R2_ 0.04f
#define ALPHA_ 0.2f
#define EPS_ 1e-5f

// ---------------- scratch (device globals: no allocations allowed) ----------------
__device__ float g_y0[(size_t)64*M_];          // layer0 raw output
__device__ float g_y1[(size_t)128*M_];         // layer1 raw output
__device__ float g_ft[(size_t)B_*N_*64];       // features transposed [B][N][64]
__device__ float g_gmax[(size_t)256*B_*Q_];    // layer2 max over S (pre-BN)
__device__ int   g_nidx[M_];                   // ball query indices
__device__ float g_st0[2*64], g_st1[2*128], g_st2[2*256];   // [sum | sumsq]
__device__ float g_ac0[2*64], g_ac1[2*128], g_ac2[2*256];   // [a | c] per channel
__device__ float g_wt0[96*64];                 // W0^T (tf32, CHANNEL-PERMUTED: ft first, rel at k=64..66)
__device__ float g_wt1[64*128];                // W1^T
__device__ float g_wt2[128*256];               // W2^T

__device__ __forceinline__ float lrelu(float v){ return v >= 0.f ? v : ALPHA_*v; }

// tf32 quantization (cuBLAS-style round-to-nearest)
__device__ __forceinline__ float tf32r(float x){
    unsigned r; asm("cvt.rna.tf32.f32 %0, %1;" : "=r"(r) : "f"(x));
    return __uint_as_float(r);
}

typedef unsigned long long u64;
__device__ __forceinline__ u64 fma2n(u64 a, u64 b, u64 c){
    u64 d; asm("fma.rn.f32x2 %0, %1, %2, %3;" : "=l"(d) : "l"(a), "l"(b), "l"(c)); return d;
}
__device__ __forceinline__ u64 add2(u64 a, u64 b){
    u64 d; asm("add.rn.f32x2 %0, %1, %2;" : "=l"(d) : "l"(a), "l"(b)); return d;
}
__device__ __forceinline__ u64 mul2(u64 a, u64 b){
    u64 d; asm("mul.rn.f32x2 %0, %1, %2;" : "=l"(d) : "l"(a), "l"(b)); return d;
}
__device__ __forceinline__ u64 pack2(float lo, float hi){
    u64 d; asm("mov.b64 %0, {%1,%2};" : "=l"(d) : "f"(lo), "f"(hi)); return d;
}
__device__ __forceinline__ u64 splat2(float v){
    u64 d; asm("mov.b64 %0, {%1,%1};" : "=l"(d) : "f"(v)); return d;
}
__device__ __forceinline__ float2 u2f2(u64 u){
    float2 f; asm("mov.b64 {%0,%1}, %2;" : "=f"(f.x), "=f"(f.y) : "l"(u)); return f;
}

// legacy tensor-core mma (sm_80+, valid on compute_100 baseline target)
__device__ __forceinline__ void mma_tf32(float* d, uint32_t a0, uint32_t a1,
                                         uint32_t a2, uint32_t a3,
                                         uint32_t b0, uint32_t b1){
    asm volatile(
        "mma.sync.aligned.m16n8k8.row.col.f32.tf32.tf32.f32 "
        "{%0,%1,%2,%3}, {%4,%5,%6,%7}, {%8,%9}, {%0,%1,%2,%3};"
        : "+f"(d[0]), "+f"(d[1]), "+f"(d[2]), "+f"(d[3])
        : "r"(a0), "r"(a1), "r"(a2), "r"(a3), "r"(b0), "r"(b1));
}

// argmax step across 32 index-ordered candidates (values >= 0)
__device__ __forceinline__ void warp_argmax(float &best, int &bi){
    unsigned bb = __float_as_uint(best);
    unsigned mx = __reduce_max_sync(0xffffffffu, bb);
    unsigned who = __ballot_sync(0xffffffffu, bb == mx);
    int src = __ffs(who) - 1;
    bi = __shfl_sync(0xffffffffu, bi, src);
    best = __uint_as_float(mx);
}

// ---------------- FPS: one block per batch, 1024 threads, single barrier/iter ----------------
// (R12/R14 proven version: 676us measured; cross-block lockstep was 5x worse)
__global__ void __launch_bounds__(1024) fps_kernel(const float* __restrict__ xyz,
                                                   float* __restrict__ newxyz){
    int b = blockIdx.x, t = threadIdx.x;
    int wid = t >> 5, lane = t & 31;
    const float* px = xyz + (size_t)b*N_*3;
    u64 X2[4], Y2[4], Z2[4];
    float D[8];
#pragma unroll
    for (int i=0;i<4;i++){
        int p0 = t*8 + 2*i, p1 = p0 + 1;
        X2[i] = pack2(px[p0*3+0], px[p1*3+0]);
        Y2[i] = pack2(px[p0*3+1], px[p1*3+1]);
        Z2[i] = pack2(px[p0*3+2], px[p1*3+2]);
        D[2*i] = 1e10f; D[2*i+1] = 1e10f;
    }
    __shared__ float s_val[2][32];
    __shared__ int   s_idx[2][32];
    float lx = px[0], ly = px[1], lz = px[2];
    if (t==0){
        newxyz[0 + (size_t)b*Q_*3]=lx;
        newxyz[1 + (size_t)b*Q_*3]=ly;
        newxyz[2 + (size_t)b*Q_*3]=lz;
    }
    for (int j=1;j<Q_;j++){
        int par = j & 1;
        u64 nlx = splat2(-lx), nly = splat2(-ly), nlz = splat2(-lz);
#pragma unroll
        for (int i=0;i<4;i++){
            u64 dx = add2(X2[i], nlx);
            u64 dy = add2(Y2[i], nly);
            u64 dz = add2(Z2[i], nlz);
            u64 tt = mul2(dx, dx);
            tt = fma2n(dy, dy, tt);
            tt = fma2n(dz, dz, tt);
            float2 d = u2f2(tt);
            D[2*i]   = fminf(D[2*i],   d.x);
            D[2*i+1] = fminf(D[2*i+1], d.y);
        }
        float vbest = fmaxf(fmaxf(fmaxf(D[0],D[1]), fmaxf(D[2],D[3])),
                            fmaxf(fmaxf(D[4],D[5]), fmaxf(D[6],D[7])));
        unsigned mx = __reduce_max_sync(0xffffffffu, __float_as_uint(vbest));
        unsigned who = __ballot_sync(0xffffffffu, __float_as_uint(vbest) == mx);
        int src = __ffs(who) - 1;
        int bi = 0;
        if (lane == src){                        // winning lane recovers index
#pragma unroll
            for (int i=7;i>=0;i--)
                if (__float_as_uint(D[i]) == mx) bi = t*8 + i;
        }
        bi = __shfl_sync(0xffffffffu, bi, src);
        if (lane==0){ s_val[par][wid]=__uint_as_float(mx); s_idx[par][wid]=bi; }
        __syncthreads();
        float best = s_val[par][lane]; bi = s_idx[par][lane];
        warp_argmax(best, bi);
        const float* pp = px + (size_t)bi*3;     // broadcast load, L1-hot
        lx = pp[0]; ly = pp[1]; lz = pp[2];
        if (t==0){
            float* o = newxyz + (size_t)(b*Q_+j)*3;
            o[0]=lx; o[1]=ly; o[2]=lz;
        }
    }
}

// ---------------- Ball query: one warp per (b,q), XLA-matched rounding ----------------
__global__ void __launch_bounds__(256) ballquery_kernel(const float* __restrict__ xyz,
                                                        const float* __restrict__ newxyz,
                                                        int* __restrict__ nidx){
    int w = (blockIdx.x*256 + threadIdx.x) >> 5;
    int lane = threadIdx.x & 31;
    int b = w >> 10;
    const float* px = xyz + (size_t)b*N_*3;
    const float* pq = newxyz + (size_t)w*3;
    float qx=pq[0], qy=pq[1], qz=pq[2];
    float qsq = __fadd_rn(__fadd_rn(__fmul_rn(qx,qx), __fmul_rn(qy,qy)), __fmul_rn(qz,qz));
    int* out = nidx + (size_t)w*S_;
    int cnt = 0, first = 0;
    for (int base=0; base<N_ && cnt<S_; base+=32){
        int p = base + lane;
        float x=px[p*3+0], y=px[p*3+1], z=px[p*3+2];
        float xsq = __fadd_rn(__fadd_rn(__fmul_rn(x,x), __fmul_rn(y,y)), __fmul_rn(z,z));
        float dot = __fmaf_rn(qz, z, __fmaf_rn(qy, y, __fmul_rn(qx, x)));
        float d2  = __fadd_rn(__fadd_rn(qsq, xsq), __fmul_rn(-2.0f, dot));
        bool in = d2 < R2_;
        unsigned bal = __ballot_sync(0xffffffffu, in);
        if (bal){
            if (cnt == 0) first = base + __ffs(bal) - 1;
            int r = __popc(bal & ((1u << lane) - 1u));
            if (in && (cnt + r < S_)) out[cnt + r] = p;
            cnt += __popc(bal);
        }
    }
    if (cnt < S_){
        int pad = (cnt > 0) ? first : 0;
        if (lane >= cnt) out[lane] = pad;
    }
}

// ---------------- merged prep: transpose_feat + 3x transpose_w + zero_stats ----------------
__global__ void __launch_bounds__(256) prep_kernel(
    const float* __restrict__ f, float* __restrict__ ft,
    const float* __restrict__ W0, float* __restrict__ WT0,
    const float* __restrict__ W1, float* __restrict__ WT1,
    const float* __restrict__ W2, float* __restrict__ WT2)
{
    int blk = blockIdx.x;
    int tid = threadIdx.x;
    if (blk < 2048){
        __shared__ float st[64][33];
        int b = blk >> 8;
        int n0 = (blk & 255) * 32;
        int nn = tid & 31, c0 = tid >> 5;
#pragma unroll
        for (int c = c0; c < 64; c += 8)
            st[c][nn] = f[((size_t)b*64 + c)*N_ + n0 + nn];
        __syncthreads();
#pragma unroll
        for (int e = tid; e < 2048; e += 256){
            int nl = e >> 6, c = e & 63;
            ft[((size_t)b*N_ + n0 + nl)*64 + c] = st[c][nl];
        }
        return;
    }
    int idx = (blk - 2048)*256 + tid;
    if (idx < 6144){                               // W0^T: 96x64, PERMUTED channels
        int k = idx / 64, c = idx - k*64;
        int ks = (k < 64) ? (k + 3) : ((k < 67) ? (k - 64) : -1);
        WT0[idx] = (ks >= 0) ? tf32r(W0[c*67 + ks]) : 0.f;
    } else if (idx < 6144 + 8192){                 // W1^T: 64x128
        int i2 = idx - 6144;
        int k = i2 / 128, c = i2 - k*128;
        WT1[i2] = tf32r(W1[c*64 + k]);
    } else if (idx < 6144 + 8192 + 32768){         // W2^T: 128x256
        int i2 = idx - 6144 - 8192;
        int k = i2 / 256, c = i2 - k*256;
        WT2[i2] = tf32r(W2[c*128 + k]);
    } else if (idx < 6144 + 8192 + 32768 + 896){   // zero stats
        int i2 = idx - 6144 - 8192 - 32768;
        if (i2 < 128)      g_st0[i2] = 0.f;
        else if (i2 < 384) g_st1[i2-128] = 0.f;
        else               g_st2[i2-384] = 0.f;
    }
}

#define PW0 36  // l0 pitch: 16B-aligned rows for float4 fill; fragment LDS conflict-free
#define PWG 37  // generic pitch: scalar fill 2-way (vs 16-way at 36); fragment LDS conflict-free

// ---------------- L0 GEMM, fused VECTORIZED gather ----------------
// Channel order: k=0..63 ft (aligned float4 gather), k=64..66 rel-xyz, rest pad.
__global__ void __launch_bounds__(256,2) mma_gemm_l0(
    const float* __restrict__ WT, const float* __restrict__ bias,
    const float* __restrict__ xyz, const float* __restrict__ nxyz,
    const float* __restrict__ ft, const int* __restrict__ nidx,
    float* __restrict__ Yout, float* __restrict__ gstats)
{
    constexpr int WY=4, WX=2, NT=8;
    constexpr int CTILE = WY*16;    // 64
    constexpr int MT = WX*NT*8;     // 128
    constexpr int NCH = 3;          // KPAD=96
    __shared__ __align__(16) float sW[CTILE*PW0];
    __shared__ __align__(16) float sX[MT*PW0];
    int tid = threadIdx.x;
    int wid = tid >> 5, lane = tid & 31;
    int wy = wid % WY, wx = wid / WY;
    int mbase = blockIdx.x * MT;
    int qr = lane >> 2, ql = lane & 3;
    int mwarp = wx*NT*8;

    int mloc = tid & 127;
    int half = tid >> 7;                 // 0: kk 0-15, 1: kk 16-31
    int m = mbase + mloc;
    int gb = m >> 15;
    int gq = (m >> 5) & (Q_-1);
    int p = nidx[m];
    const float* pc = xyz + ((size_t)gb*N_ + p)*3;
    const float* qc = nxyz + ((size_t)(gb*Q_ + gq))*3;
    float rel0 = pc[0]-qc[0], rel1 = pc[1]-qc[1], rel2 = pc[2]-qc[2];
    const float* fr = ft + ((size_t)gb*N_ + p)*64;

    float d[NT][4];
#pragma unroll
    for (int i=0;i<NT;i++){ d[i][0]=0.f; d[i][1]=0.f; d[i][2]=0.f; d[i][3]=0.f; }

#pragma unroll 1
    for (int ch = 0; ch < NCH; ++ch){
        int k0 = ch*32;
        __syncthreads();
#pragma unroll
        for (int e = tid; e < CTILE*8; e += 256){
            int kk = e / (CTILE/4), c4 = e % (CTILE/4);
            float4 w = *(const float4*)&WT[(size_t)(k0+kk)*64 + c4*4];
            sW[(c4*4+0)*PW0 + kk] = w.x;
            sW[(c4*4+1)*PW0 + kk] = w.y;
            sW[(c4*4+2)*PW0 + kk] = w.z;
            sW[(c4*4+3)*PW0 + kk] = w.w;
        }
        if (ch < 2){
            const float4* f4 = (const float4*)(fr + ch*32 + half*16);
#pragma unroll
            for (int j=0;j<4;j++){
                float4 v = f4[j];
                v.x=tf32r(v.x); v.y=tf32r(v.y); v.z=tf32r(v.z); v.w=tf32r(v.w);
                *(float4*)&sX[mloc*PW0 + half*16 + j*4] = v;
            }
        } else {
            float4 z = make_float4(0.f,0.f,0.f,0.f);
            if (half==0){
                *(float4*)&sX[mloc*PW0 + 0]  = make_float4(tf32r(rel0), tf32r(rel1), tf32r(rel2), 0.f);
                *(float4*)&sX[mloc*PW0 + 4]  = z;
                *(float4*)&sX[mloc*PW0 + 8]  = z;
                *(float4*)&sX[mloc*PW0 + 12] = z;
            } else {
#pragma unroll
                for (int j=0;j<4;j++) *(float4*)&sX[mloc*PW0 + 16 + j*4] = z;
            }
        }
        __syncthreads();
#pragma unroll
        for (int s = 0; s < 4; ++s){
            int kb = s*8 + ql;
            const float* w0 = &sW[(wy*16 + qr)*PW0];
            const float* w8 = &sW[(wy*16 + qr + 8)*PW0];
            uint32_t a0 = __float_as_uint(w0[kb]);
            uint32_t a1 = __float_as_uint(w8[kb]);
            uint32_t a2 = __float_as_uint(w0[kb+4]);
            uint32_t a3 = __float_as_uint(w8[kb+4]);
#pragma unroll
            for (int nt = 0; nt < NT; ++nt){
                const float* xb = &sX[(mwarp + nt*8 + qr)*PW0 + s*8 + ql];
                uint32_t b0 = __float_as_uint(xb[0]);
                uint32_t b1 = __float_as_uint(xb[4]);
                mma_tf32(d[nt], a0, a1, a2, a3, b0, b1);
            }
        }
    }

    int cout0 = wy*16 + qr;
    int cout1 = cout0 + 8;
    float bi0 = bias[cout0], bi1 = bias[cout1];
    float s1a=0.f, s2a=0.f, s1b=0.f, s2b=0.f;
#pragma unroll
    for (int nt = 0; nt < NT; ++nt){
        float v0 = d[nt][0] + bi0, v1 = d[nt][1] + bi0;
        float v2 = d[nt][2] + bi1, v3 = d[nt][3] + bi1;
        s1a += v0 + v1;  s2a += v0*v0 + v1*v1;
        s1b += v2 + v3;  s2b += v2*v2 + v3*v3;
        int m0 = mbase + mwarp + nt*8 + ql*2;
        *(float2*)(Yout + (size_t)cout0*M_ + m0) = make_float2(v0, v1);
        *(float2*)(Yout + (size_t)cout1*M_ + m0) = make_float2(v2, v3);
    }
#pragma unroll
    for (int o=1;o<4;o<<=1){
        s1a += __shfl_xor_sync(0xffffffffu, s1a, o);
        s2a += __shfl_xor_sync(0xffffffffu, s2a, o);
        s1b += __shfl_xor_sync(0xffffffffu, s1b, o);
        s2b += __shfl_xor_sync(0xffffffffu, s2b, o);
    }
    if (ql == 0){
        atomicAdd(&gstats[cout0], s1a);
        atomicAdd(&gstats[64 + cout0], s2a);
        atomicAdd(&gstats[cout1], s1b);
        atomicAdd(&gstats[64 + cout1], s2b);
    }
}

// ---------------- Generic GEMM via mma.sync m16n8k8 TF32 (PW=37, R12-proven) ----------------
template<int CIN, int KPAD, int WY, int WX, int NT, bool TRANS, bool DOMAX, int COUTTOT>
__global__ void __launch_bounds__(256,2) mma_gemm(
    const float* __restrict__ WT, const float* __restrict__ bias,
    const float* __restrict__ Xin, const float* __restrict__ ac,
    float* __restrict__ Yout, float* __restrict__ gstats, float* __restrict__ gmax)
{
    constexpr int CTILE = WY*16;
    constexpr int MT = WX*NT*8;
    constexpr int NCH = KPAD/32;
    __shared__ float sW[CTILE*PWG];
    __shared__ float sX[MT*PWG];
    int tid = threadIdx.x;
    int wid = tid >> 5, lane = tid & 31;
    int wy = wid % WY, wx = wid / WY;
    int mbase = blockIdx.x * MT;
    int cbase = blockIdx.y * CTILE;
    int qr = lane >> 2, ql = lane & 3;
    int mwarp = wx*NT*8;

    float d[NT][4];
#pragma unroll
    for (int i=0;i<NT;i++){ d[i][0]=0.f; d[i][1]=0.f; d[i][2]=0.f; d[i][3]=0.f; }

#pragma unroll 1
    for (int ch = 0; ch < NCH; ++ch){
        int k0 = ch*32;
        __syncthreads();
#pragma unroll
        for (int e = tid; e < CTILE*8; e += 256){
            int kk = e / (CTILE/4), c4 = e % (CTILE/4);
            float4 w = *(const float4*)&WT[(size_t)(k0+kk)*COUTTOT + cbase + c4*4];
            sW[(c4*4+0)*PWG + kk] = w.x;
            sW[(c4*4+1)*PWG + kk] = w.y;
            sW[(c4*4+2)*PWG + kk] = w.z;
            sW[(c4*4+3)*PWG + kk] = w.w;
        }
#pragma unroll
        for (int e = tid; e < MT*8; e += 256){
            int kk = e / (MT/4), m4 = e % (MT/4);
            int k = k0 + kk;
            float4 v = make_float4(0.f,0.f,0.f,0.f);
            if (k < CIN){
                v = *(const float4*)(Xin + (size_t)k*M_ + mbase + m4*4);
                if constexpr (TRANS){
                    float a = ac[k], c2 = ac[CIN + k];
                    v.x = lrelu(a*v.x + c2);
                    v.y = lrelu(a*v.y + c2);
                    v.z = lrelu(a*v.z + c2);
                    v.w = lrelu(a*v.w + c2);
                }
                v.x = tf32r(v.x); v.y = tf32r(v.y);
                v.z = tf32r(v.z); v.w = tf32r(v.w);
            }
            sX[(m4*4+0)*PWG + kk] = v.x;
            sX[(m4*4+1)*PWG + kk] = v.y;
            sX[(m4*4+2)*PWG + kk] = v.z;
            sX[(m4*4+3)*PWG + kk] = v.w;
        }
        __syncthreads();
#pragma unroll
        for (int s = 0; s < 4; ++s){
            int kb = s*8 + ql;
            const float* w0 = &sW[(wy*16 + qr)*PWG];
            const float* w8 = &sW[(wy*16 + qr + 8)*PWG];
            uint32_t a0 = __float_as_uint(w0[kb]);
            uint32_t a1 = __float_as_uint(w8[kb]);
            uint32_t a2 = __float_as_uint(w0[kb+4]);
            uint32_t a3 = __float_as_uint(w8[kb+4]);
#pragma unroll
            for (int nt = 0; nt < NT; ++nt){
                const float* xb = &sX[(mwarp + nt*8 + qr)*PWG + s*8 + ql];
                uint32_t b0 = __float_as_uint(xb[0]);
                uint32_t b1 = __float_as_uint(xb[4]);
                mma_tf32(d[nt], a0, a1, a2, a3, b0, b1);
            }
        }
    }

    // -------- epilogue --------
    int cout0 = cbase + wy*16 + qr;
    int cout1 = cout0 + 8;
    float bi0 = bias[cout0], bi1 = bias[cout1];
    float s1a=0.f, s2a=0.f, s1b=0.f, s2b=0.f;
    float mxa[NT/4], mxb[NT/4];
#pragma unroll
    for (int g=0; g<NT/4; ++g){ mxa[g] = -1e30f; mxb[g] = -1e30f; }
#pragma unroll
    for (int nt = 0; nt < NT; ++nt){
        float v0 = d[nt][0] + bi0, v1 = d[nt][1] + bi0;
        float v2 = d[nt][2] + bi1, v3 = d[nt][3] + bi1;
        s1a += v0 + v1;  s2a += v0*v0 + v1*v1;
        s1b += v2 + v3;  s2b += v2*v2 + v3*v3;
        if constexpr (DOMAX){
            int g = nt >> 2;
            mxa[g] = fmaxf(mxa[g], fmaxf(v0, v1));
            mxb[g] = fmaxf(mxb[g], fmaxf(v2, v3));
        } else {
            int m0 = mbase + mwarp + nt*8 + ql*2;
            *(float2*)(Yout + (size_t)cout0*M_ + m0) = make_float2(v0, v1);
            *(float2*)(Yout + (size_t)cout1*M_ + m0) = make_float2(v2, v3);
        }
    }
#pragma unroll
    for (int o=1;o<4;o<<=1){
        s1a += __shfl_xor_sync(0xffffffffu, s1a, o);
        s2a += __shfl_xor_sync(0xffffffffu, s2a, o);
        s1b += __shfl_xor_sync(0xffffffffu, s1b, o);
        s2b += __shfl_xor_sync(0xffffffffu, s2b, o);
    }
    if constexpr (DOMAX){
#pragma unroll
        for (int g=0; g<NT/4; ++g){
#pragma unroll
            for (int o=1;o<4;o<<=1){
                mxa[g] = fmaxf(mxa[g], __shfl_xor_sync(0xffffffffu, mxa[g], o));
                mxb[g] = fmaxf(mxb[g], __shfl_xor_sync(0xffffffffu, mxb[g], o));
            }
        }
        if (ql == 0){
            int sg = (mbase + mwarp) >> 5;
#pragma unroll
            for (int g=0; g<NT/4; ++g){
                gmax[(size_t)cout0*(B_*Q_) + sg + g] = mxa[g];
                gmax[(size_t)cout1*(B_*Q_) + sg + g] = mxb[g];
            }
        }
    }
    if (ql == 0){
        atomicAdd(&gstats[cout0], s1a);
        atomicAdd(&gstats[COUTTOT + cout0], s2a);
        atomicAdd(&gstats[cout1], s1b);
        atomicAdd(&gstats[COUTTOT + cout1], s2b);
    }
}

template<int COUT>
__global__ void compute_ac(const float* __restrict__ st, const float* __restrict__ g,
                           const float* __restrict__ beta, float* __restrict__ ac){
    int c = threadIdx.x;
    if (c >= COUT) return;
    float inv  = 1.f/(float)M_;
    float mean = st[c]*inv;
    float var  = st[COUT+c]*inv - mean*mean;
    float a    = g[c]*rsqrtf(var + EPS_);
    ac[c]      = a;
    ac[COUT+c] = beta[c] - a*mean;
}

// out[b][c][q] = leaky(a2[c]*max + c2[c])   (BN+LeakyReLU commute with max since a2>0)
__global__ void __launch_bounds__(256) final_kernel(const float* __restrict__ gmax,
                                                    const float* __restrict__ ac,
                                                    float* __restrict__ out){
    int i = blockIdx.x*256 + threadIdx.x;
    int q = i & (Q_-1);
    int c = (i >> 10) & 255;
    int b = i >> 18;
    float a = ac[c], c2 = ac[256+c];
    out[i] = lrelu(a*gmax[(size_t)c*(B_*Q_) + b*Q_ + q] + c2);
}

extern "C" void kernel_launch(void* const* d_in, const int* in_sizes, int n_in,
                              void* d_out, int out_size) {
    const float* xyz  = (const float*)d_in[0];
    const float* feat = (const float*)d_in[1];
    const float* W0 = (const float*)d_in[2];
    const float* b0 = (const float*)d_in[3];
    const float* gg0= (const float*)d_in[4];
    const float* be0= (const float*)d_in[5];
    const float* W1 = (const float*)d_in[6];
    const float* b1 = (const float*)d_in[7];
    const float* gg1= (const float*)d_in[8];
    const float* be1= (const float*)d_in[9];
    const float* W2 = (const float*)d_in[10];
    const float* b2 = (const float*)d_in[11];
    const float* gg2= (const float*)d_in[12];
    const float* be2= (const float*)d_in[13];

    float* out = (float*)d_out;
    float* newxyz  = out;                          // [B][Q][3]
    float* outfeat = out + (size_t)B_*Q_*3;        // [B][256][Q]

    float *y0p,*y1p,*ftp,*gmaxp,*st0p,*st1p,*st2p,*ac0p,*ac1p,*ac2p;
    float *wt0p,*wt1p,*wt2p; int* idxp;
    cudaGetSymbolAddress((void**)&y0p,  g_y0);
    cudaGetSymbolAddress((void**)&y1p,  g_y1);
    cudaGetSymbolAddress((void**)&ftp,  g_ft);
    cudaGetSymbolAddress((void**)&gmaxp,g_gmax);
    cudaGetSymbolAddress((void**)&idxp, g_nidx);
    cudaGetSymbolAddress((void**)&st0p, g_st0);
    cudaGetSymbolAddress((void**)&st1p, g_st1);
    cudaGetSymbolAddress((void**)&st2p, g_st2);
    cudaGetSymbolAddress((void**)&ac0p, g_ac0);
    cudaGetSymbolAddress((void**)&ac1p, g_ac1);
    cudaGetSymbolAddress((void**)&ac2p, g_ac2);
    cudaGetSymbolAddress((void**)&wt0p, g_wt0);
    cudaGetSymbolAddress((void**)&wt1p, g_wt1);
    cudaGetSymbolAddress((void**)&wt2p, g_wt2);

    prep_kernel<<<2048 + 188, 256>>>(feat, ftp, W0, wt0p, W1, wt1p, W2, wt2p);
    fps_kernel<<<B_, 1024>>>(xyz, newxyz);
    ballquery_kernel<<<(B_*Q_)/8, 256>>>(xyz, newxyz, idxp);

    // L0 in profiled slot #4: fused vectorized gather, 64 cout x 128 m
    mma_gemm_l0<<<M_/128, 256>>>(wt0p, b0, xyz, newxyz, ftp, idxp, y0p, st0p);
    compute_ac<64><<<1, 64>>>(st0p, gg0, be0, ac0p);

    // L1: 128 cout x 64 m
    mma_gemm<64,64,8,1,8,true,false,128><<<dim3(M_/64, 1), 256>>>(
        wt1p, b1, y0p, ac0p, y1p, st1p, nullptr);
    compute_ac<128><<<1, 128>>>(st1p, gg1, be1, ac1p);

    // L2: 2 tiles of 128 cout x 64 m, fused max-over-S
    mma_gemm<128,128,8,1,8,true,true,256><<<dim3(M_/64, 2), 256>>>(
        wt2p, b2, y1p, ac1p, nullptr, st2p, gmaxp);
    compute_ac<256><<<1, 256>>>(st2p, gg2, be2, ac2p);

    final_kernel<<<(B_*256*Q_)/256, 256>>>(gmaxp, ac2p, outfeat);
}